// round 16
// baseline (speedup 1.0000x reference)
#include <cuda_runtime.h>
#include <cuda_fp16.h>
#include <math.h>
#include <stdint.h>

// Problem constants
#define NN 50000
#define EE 800000
#define CC 128
#define HH 8
#define TT 8

// ---------------- scratch (device globals) -------------------------------------
__device__ __half g_qkv16[(size_t)3 * NN * CC];      // q16, k16, v16 contiguous
__device__ __half g_feat16[(size_t)NN * CC];
__device__ __half g_hn16[(size_t)NN * CC];
__device__ __half g_vt16[(size_t)TT * NN * CC];
__device__ __half g_hmid16[(size_t)NN * 4 * CC];
__device__ float g_escore[(size_t)EE * HH];
__device__ float g_den[(size_t)NN * HH];
__device__ float g_wv[(size_t)NN * CC];
__device__ float g_feat1[(size_t)NN * CC];
__device__ float g_bias_qkv[3 * CC];

// fp16 weights
#define WOFF_Q    0
#define WOFF_K    16384
#define WOFF_V    32768
#define WOFF_REL  49152
#define WOFF_PROJ 180224
#define WOFF_EW   196608
#define WOFF_W1   212992
#define WOFF_W2   278528
#define WBF_TOTAL 344064
__device__ __half g_wh[WBF_TOTAL];

// ---------------- helpers -----------------------------------------------------------
__device__ __forceinline__ uint32_t half2_u(__half2 v) {
    return *reinterpret_cast<uint32_t*>(&v);
}
__device__ __forceinline__ uint32_t smem_u32(const void* p) {
    uint32_t addr;
    asm("{ .reg .u64 t; cvta.to.shared.u64 t, %1; cvt.u32.u64 %0, t; }"
        : "=r"(addr) : "l"(p));
    return addr;
}
__device__ __forceinline__ void ldsm_x4(uint32_t* r, uint32_t addr) {
    asm volatile("ldmatrix.sync.aligned.m8n8.x4.shared.b16 {%0,%1,%2,%3}, [%4];"
                 : "=r"(r[0]), "=r"(r[1]), "=r"(r[2]), "=r"(r[3]) : "r"(addr));
}
__device__ __forceinline__ void ldsm_x4_t(uint32_t* r, uint32_t addr) {
    asm volatile("ldmatrix.sync.aligned.m8n8.x4.trans.shared.b16 {%0,%1,%2,%3}, [%4];"
                 : "=r"(r[0]), "=r"(r[1]), "=r"(r[2]), "=r"(r[3]) : "r"(addr));
}
__device__ __forceinline__ void mma16816(float* c, const uint32_t* a, const uint32_t* b) {
    asm volatile(
        "mma.sync.aligned.m16n8k16.row.col.f32.f16.f16.f32 "
        "{%0,%1,%2,%3}, {%4,%5,%6,%7}, {%8,%9}, {%0,%1,%2,%3};"
        : "+f"(c[0]), "+f"(c[1]), "+f"(c[2]), "+f"(c[3])
        : "r"(a[0]), "r"(a[1]), "r"(a[2]), "r"(a[3]), "r"(b[0]), "r"(b[1]));
}
__device__ __forceinline__ void cp16(uint32_t dst, const void* src) {
    asm volatile("cp.async.cg.shared.global [%0], [%1], 16;"
                 :: "r"(dst), "l"(src) : "memory");
}
__device__ __forceinline__ void cp16z(uint32_t dst, const void* src, int bytes) {
    asm volatile("cp.async.cg.shared.global [%0], [%1], 16, %2;"
                 :: "r"(dst), "l"(src), "r"(bytes) : "memory");
}
__device__ __forceinline__ void cp_commit() {
    asm volatile("cp.async.commit_group;" ::: "memory");
}
__device__ __forceinline__ void cp_wait0() {
    asm volatile("cp.async.wait_group 0;" ::: "memory");
}
__device__ __forceinline__ void cp_wait2() {
    asm volatile("cp.async.wait_group 2;" ::: "memory");
}

__device__ __forceinline__ uint32_t a_swz(int r, int c16) {
    return (uint32_t)r * 64u + (uint32_t)((c16 ^ ((r >> 1) & 3)) << 4);
}
__device__ __forceinline__ uint32_t b_swz(int k, int c16) {
    return (uint32_t)k * 256u + (uint32_t)((c16 ^ (k & 7)) << 4);
}
__device__ __forceinline__ float gelu1(float v) {
    return 0.5f * v * (1.0f + erff(v * 0.70710678118654752f));
}

// =====================================================================================
// STREAM GEMM (fp16 A, K = 128): B (128x128 fp16, 32KB) fully resident in smem.
// =====================================================================================
#define SBS 0
#define SAS 32768
#define SMS_TOTAL 65536

__global__ void __launch_bounds__(256, 3) gemm_stream_kernel(
    const __half* __restrict__ Ah, int ldx,
    const __half* __restrict__ Bh, int ldw, size_t w_y_off, int col_y,
    const float* __restrict__ bias, int bias_y_off,
    float* __restrict__ outF, int ldo, size_t out_y_off,
    __half* __restrict__ outH, int halfMode,
    int M, int doGelu, int nBlk)
{
    extern __shared__ char smem[];
    const uint32_t sb = smem_u32(smem);
    const int tid  = threadIdx.x;
    const int wid  = tid >> 5;
    const int lane = tid & 31;
    const int wm   = wid & 1;
    const int wn   = wid >> 1;
    const int wcol0 = blockIdx.y * col_y;

    Bh += (size_t)blockIdx.y * w_y_off;
    if (outF) outF += (size_t)blockIdx.y * out_y_off;
    if (halfMode == 2 && outH) outH += (size_t)blockIdx.y * out_y_off;
    if (bias) bias += (size_t)blockIdx.y * bias_y_off;

#pragma unroll
    for (int i = 0; i < 8; i++) {
        int idx = tid + i * 256;
        int kk = idx >> 4, c16 = idx & 15;
        cp16(sb + SBS + (uint32_t)kk * 256u + (uint32_t)((c16 ^ (kk & 7)) << 4),
             Bh + (size_t)kk * ldw + wcol0 + c16 * 8);
    }
    cp_commit();

#define PREF_A(blk, st) do {                                                       \
        uint32_t base = sb + SAS + (uint32_t)(st) * 16384u;                        \
        _Pragma("unroll")                                                          \
        for (int i = 0; i < 4; i++) {                                              \
            int idx = tid + i * 256;                                               \
            int r = idx >> 4, c16 = idx & 15;                                      \
            int row = (blk) * 64 + r;                                              \
            int bytes = (row < M) ? 16 : 0;                                        \
            cp16z(base + (uint32_t)r * 256u + (uint32_t)((c16 ^ (r & 7)) << 4),    \
                  Ah + (size_t)row * ldx + c16 * 8, bytes);                        \
        }                                                                          \
    } while (0)

    PREF_A(blockIdx.x, 0);
    cp_commit();

    const int a_r  = wm * 32 + (lane & 15);
    const int a_k8 = (lane >> 4) << 3;
    const int b_k  = (((lane >> 3) & 1) << 3) + (lane & 7);
    const int b_n  = wn * 32 + ((lane >> 4) << 3);
    const int g = lane >> 2;
    const int t = lane & 3;
    const bool h16 = (halfMode == 2);

    int iter = 0;
    for (int blk = blockIdx.x; blk < nBlk; blk += gridDim.x, iter++) {
        const int st = iter & 1;
        const uint32_t abase = sb + SAS + (uint32_t)st * 16384u;

        cp_wait0();
        __syncthreads();

        int nxt = blk + gridDim.x;
        if (nxt < nBlk) PREF_A(nxt, st ^ 1);
        cp_commit();

        float acc[2][4][4];
#pragma unroll
        for (int i = 0; i < 2; i++)
#pragma unroll
            for (int j = 0; j < 4; j++)
#pragma unroll
                for (int l = 0; l < 4; l++) acc[i][j][l] = 0.0f;

#pragma unroll
        for (int ks = 0; ks < 8; ks++) {
            const int k0 = ks * 16;
            uint32_t bh[4][2];
            {
                int kk = k0 + b_k;
#pragma unroll
                for (int pair = 0; pair < 2; pair++) {
                    int n = b_n + pair * 16;
                    uint32_t addr = (uint32_t)kk * 256u
                        + (((uint32_t)(n * 2)) ^ (uint32_t)((kk & 7) << 4));
                    uint32_t r[4];
                    ldsm_x4_t(r, sb + SBS + addr);
                    bh[2 * pair][0] = r[0]; bh[2 * pair][1] = r[1];
                    bh[2 * pair + 1][0] = r[2]; bh[2 * pair + 1][1] = r[3];
                }
            }
            uint32_t a[2][4];
            {
                int kk = k0 + a_k8;
#pragma unroll
                for (int mf = 0; mf < 2; mf++) {
                    int r = a_r + mf * 16;
                    uint32_t addr = (uint32_t)r * 256u
                        + (((uint32_t)(kk * 2)) ^ (uint32_t)((r & 7) << 4));
                    ldsm_x4(a[mf], abase + addr);
                }
            }
#pragma unroll
            for (int mf = 0; mf < 2; mf++)
#pragma unroll
                for (int nf = 0; nf < 4; nf++)
                    mma16816(acc[mf][nf], a[mf], bh[nf]);
        }
        __syncthreads();

        const int row0 = blk * 64;
#pragma unroll
        for (int mf = 0; mf < 2; mf++) {
#pragma unroll
            for (int nf = 0; nf < 4; nf++) {
                int cl = wn * 32 + nf * 8 + 2 * t;
                float b0 = 0.f, b1 = 0.f;
                if (bias) { b0 = bias[wcol0 + cl]; b1 = bias[wcol0 + cl + 1]; }
#pragma unroll
                for (int half = 0; half < 2; half++) {
                    int r = row0 + wm * 32 + mf * 16 + g + half * 8;
                    if (r >= M) continue;
                    float v0 = acc[mf][nf][2 * half]     + b0;
                    float v1 = acc[mf][nf][2 * half + 1] + b1;
                    if (doGelu) { v0 = gelu1(v0); v1 = gelu1(v1); }
                    if (h16) {
                        *(__half2*)&outH[(size_t)r * ldo + wcol0 + cl]
                            = __floats2half2_rn(v0, v1);
                    } else {
                        *(float2*)&outF[(size_t)r * ldo + wcol0 + cl]
                            = make_float2(v0, v1);
                    }
                }
            }
        }
    }
#undef PREF_A
}

// =====================================================================================
// STREAM GEMM fp32 A (K = 128), B resident. For proj (res supported).
// =====================================================================================
__global__ void __launch_bounds__(256, 2) gemm_stream_f32_kernel(
    const float* __restrict__ Xf, int ldx,
    const __half* __restrict__ Bh, int ldw,
    const float* __restrict__ bias,
    const float* __restrict__ res,
    float* __restrict__ outF, int ldo,
    int M, int nBlk)
{
    extern __shared__ char smem[];
    const uint32_t sb = smem_u32(smem);
    const int tid  = threadIdx.x;
    const int wid  = tid >> 5;
    const int lane = tid & 31;
    const int wm   = wid & 1;
    const int wn   = wid >> 1;

#pragma unroll
    for (int i = 0; i < 8; i++) {
        int idx = tid + i * 256;
        int kk = idx >> 4, c16 = idx & 15;
        cp16(sb + SBS + (uint32_t)kk * 256u + (uint32_t)((c16 ^ (kk & 7)) << 4),
             Bh + (size_t)kk * ldw + c16 * 8);
    }
    cp_commit();

    float4 ap[8];

#define LDG_BLK(blk) do {                                                          \
        _Pragma("unroll")                                                          \
        for (int i = 0; i < 8; i++) {                                              \
            int idx = tid + i * 256;                                               \
            int r = idx >> 5, c4 = idx & 31;                                       \
            int row = (blk) * 64 + r;                                              \
            ap[i] = (row < M)                                                      \
                ? *(const float4*)&Xf[(size_t)row * ldx + c4 * 4]                  \
                : make_float4(0.f, 0.f, 0.f, 0.f);                                 \
        }                                                                          \
    } while (0)

#define STS_BLK(st) do {                                                           \
        uint32_t base = SAS + (uint32_t)(st) * 16384u;                             \
        _Pragma("unroll")                                                          \
        for (int i = 0; i < 8; i++) {                                              \
            int idx = tid + i * 256;                                               \
            int r = idx >> 5, c4 = idx & 31;                                       \
            __half2 h0 = __floats2half2_rn(ap[i].x, ap[i].y);                      \
            __half2 h1 = __floats2half2_rn(ap[i].z, ap[i].w);                      \
            uint32_t off = base + (uint32_t)r * 256u                               \
                + (uint32_t)((((c4 >> 1) ^ (r & 7)) << 4) + ((c4 & 1) << 3));      \
            *(uint2*)(smem + off) = make_uint2(half2_u(h0), half2_u(h1));          \
        }                                                                          \
    } while (0)

    LDG_BLK(blockIdx.x);
    cp_wait0();

    const int a_r  = wm * 32 + (lane & 15);
    const int a_k8 = (lane >> 4) << 3;
    const int b_k  = (((lane >> 3) & 1) << 3) + (lane & 7);
    const int b_n  = wn * 32 + ((lane >> 4) << 3);
    const int g = lane >> 2;
    const int t = lane & 3;

    int iter = 0;
    for (int blk = blockIdx.x; blk < nBlk; blk += gridDim.x, iter++) {
        const int st = iter & 1;
        const uint32_t abase = sb + SAS + (uint32_t)st * 16384u;

        STS_BLK(st);
        __syncthreads();

        int nxt = blk + gridDim.x;
        if (nxt < nBlk) LDG_BLK(nxt);

        float acc[2][4][4];
#pragma unroll
        for (int i = 0; i < 2; i++)
#pragma unroll
            for (int j = 0; j < 4; j++)
#pragma unroll
                for (int l = 0; l < 4; l++) acc[i][j][l] = 0.0f;

#pragma unroll
        for (int ks = 0; ks < 8; ks++) {
            const int k0 = ks * 16;
            uint32_t bh[4][2];
            {
                int kk = k0 + b_k;
#pragma unroll
                for (int pair = 0; pair < 2; pair++) {
                    int n = b_n + pair * 16;
                    uint32_t addr = (uint32_t)kk * 256u
                        + (((uint32_t)(n * 2)) ^ (uint32_t)((kk & 7) << 4));
                    uint32_t r[4];
                    ldsm_x4_t(r, sb + SBS + addr);
                    bh[2 * pair][0] = r[0]; bh[2 * pair][1] = r[1];
                    bh[2 * pair + 1][0] = r[2]; bh[2 * pair + 1][1] = r[3];
                }
            }
            uint32_t a[2][4];
            {
                int kk = k0 + a_k8;
#pragma unroll
                for (int mf = 0; mf < 2; mf++) {
                    int r = a_r + mf * 16;
                    uint32_t addr = (uint32_t)r * 256u
                        + (((uint32_t)(kk * 2)) ^ (uint32_t)((r & 7) << 4));
                    ldsm_x4(a[mf], abase + addr);
                }
            }
#pragma unroll
            for (int mf = 0; mf < 2; mf++)
#pragma unroll
                for (int nf = 0; nf < 4; nf++)
                    mma16816(acc[mf][nf], a[mf], bh[nf]);
        }

        const int row0 = blk * 64;
#pragma unroll
        for (int mf = 0; mf < 2; mf++) {
#pragma unroll
            for (int nf = 0; nf < 4; nf++) {
                int cl = wn * 32 + nf * 8 + 2 * t;
                float b0 = 0.f, b1 = 0.f;
                if (bias) { b0 = bias[cl]; b1 = bias[cl + 1]; }
#pragma unroll
                for (int half = 0; half < 2; half++) {
                    int r = row0 + wm * 32 + mf * 16 + g + half * 8;
                    if (r >= M) continue;
                    float v0 = acc[mf][nf][2 * half]     + b0;
                    float v1 = acc[mf][nf][2 * half + 1] + b1;
                    if (res) {
                        float2 rv = *(const float2*)&res[(size_t)r * 128 + cl];
                        v0 += rv.x; v1 += rv.y;
                    }
                    *(float2*)&outF[(size_t)r * ldo + cl] = make_float2(v0, v1);
                }
            }
        }
    }
#undef LDG_BLK
#undef STS_BLK
}

// =====================================================================================
// FUSED ew GEMM + edge aggregation. Per 64-edge block: GEMM writes out_efeat;
// then each warp aggregates 8 edges using the smem-staged fp16 efeat.
// =====================================================================================
__global__ void __launch_bounds__(256, 2) ew_agg_kernel(
    const float* __restrict__ efeat,
    const __half* __restrict__ Bh, int ldw,
    const float* __restrict__ bias,
    float* __restrict__ outF,
    const __half* __restrict__ vt, const float* __restrict__ escore,
    const float* __restrict__ den,
    const int* __restrict__ src, const int* __restrict__ dst,
    const int* __restrict__ etype,
    float* __restrict__ wv, int Nn,
    int M, int nBlk)
{
    extern __shared__ char smem[];
    const uint32_t sb = smem_u32(smem);
    const int tid  = threadIdx.x;
    const int wid  = tid >> 5;
    const int lane = tid & 31;
    const int wm   = wid & 1;
    const int wn   = wid >> 1;

#pragma unroll
    for (int i = 0; i < 8; i++) {
        int idx = tid + i * 256;
        int kk = idx >> 4, c16 = idx & 15;
        cp16(sb + SBS + (uint32_t)kk * 256u + (uint32_t)((c16 ^ (kk & 7)) << 4),
             Bh + (size_t)kk * ldw + c16 * 8);
    }
    cp_commit();

    float4 ap[8];

#define LDG_BLK(blk) do {                                                          \
        _Pragma("unroll")                                                          \
        for (int i = 0; i < 8; i++) {                                              \
            int idx = tid + i * 256;                                               \
            int r = idx >> 5, c4 = idx & 31;                                       \
            int row = (blk) * 64 + r;                                              \
            ap[i] = (row < M)                                                      \
                ? *(const float4*)&efeat[(size_t)row * CC + c4 * 4]                \
                : make_float4(0.f, 0.f, 0.f, 0.f);                                 \
        }                                                                          \
    } while (0)

#define STS_BLK(st) do {                                                           \
        uint32_t base = SAS + (uint32_t)(st) * 16384u;                             \
        _Pragma("unroll")                                                          \
        for (int i = 0; i < 8; i++) {                                              \
            int idx = tid + i * 256;                                               \
            int r = idx >> 5, c4 = idx & 31;                                       \
            __half2 h0 = __floats2half2_rn(ap[i].x, ap[i].y);                      \
            __half2 h1 = __floats2half2_rn(ap[i].z, ap[i].w);                      \
            uint32_t off = base + (uint32_t)r * 256u                               \
                + (uint32_t)((((c4 >> 1) ^ (r & 7)) << 4) + ((c4 & 1) << 3));      \
            *(uint2*)(smem + off) = make_uint2(half2_u(h0), half2_u(h1));          \
        }                                                                          \
    } while (0)

    LDG_BLK(blockIdx.x);
    cp_wait0();

    const int a_r  = wm * 32 + (lane & 15);
    const int a_k8 = (lane >> 4) << 3;
    const int b_k  = (((lane >> 3) & 1) << 3) + (lane & 7);
    const int b_n  = wn * 32 + ((lane >> 4) << 3);
    const int g = lane >> 2;
    const int t = lane & 3;
    const int hh = lane >> 2;                 // head for agg (col group lane*4)

    int iter = 0;
    for (int blk = blockIdx.x; blk < nBlk; blk += gridDim.x, iter++) {
        const int st = iter & 1;
        const uint32_t abase = sb + SAS + (uint32_t)st * 16384u;

        STS_BLK(st);
        __syncthreads();

        int nxt = blk + gridDim.x;
        if (nxt < nBlk) LDG_BLK(nxt);

        float acc[2][4][4];
#pragma unroll
        for (int i = 0; i < 2; i++)
#pragma unroll
            for (int j = 0; j < 4; j++)
#pragma unroll
                for (int l = 0; l < 4; l++) acc[i][j][l] = 0.0f;

#pragma unroll
        for (int ks = 0; ks < 8; ks++) {
            const int k0 = ks * 16;
            uint32_t bh[4][2];
            {
                int kk = k0 + b_k;
#pragma unroll
                for (int pair = 0; pair < 2; pair++) {
                    int n = b_n + pair * 16;
                    uint32_t addr = (uint32_t)kk * 256u
                        + (((uint32_t)(n * 2)) ^ (uint32_t)((kk & 7) << 4));
                    uint32_t r[4];
                    ldsm_x4_t(r, sb + SBS + addr);
                    bh[2 * pair][0] = r[0]; bh[2 * pair][1] = r[1];
                    bh[2 * pair + 1][0] = r[2]; bh[2 * pair + 1][1] = r[3];
                }
            }
            uint32_t a[2][4];
            {
                int kk = k0 + a_k8;
#pragma unroll
                for (int mf = 0; mf < 2; mf++) {
                    int r = a_r + mf * 16;
                    uint32_t addr = (uint32_t)r * 256u
                        + (((uint32_t)(kk * 2)) ^ (uint32_t)((r & 7) << 4));
                    ldsm_x4(a[mf], abase + addr);
                }
            }
#pragma unroll
            for (int mf = 0; mf < 2; mf++)
#pragma unroll
                for (int nf = 0; nf < 4; nf++)
                    mma16816(acc[mf][nf], a[mf], bh[nf]);
        }

        const int row0 = blk * 64;
        // ---- GEMM epilogue: out_efeat ----
#pragma unroll
        for (int mf = 0; mf < 2; mf++) {
#pragma unroll
            for (int nf = 0; nf < 4; nf++) {
                int cl = wn * 32 + nf * 8 + 2 * t;
                float b0 = bias[cl], b1 = bias[cl + 1];
#pragma unroll
                for (int half = 0; half < 2; half++) {
                    int r = row0 + wm * 32 + mf * 16 + g + half * 8;
                    if (r >= M) continue;
                    float v0 = acc[mf][nf][2 * half]     + b0;
                    float v1 = acc[mf][nf][2 * half + 1] + b1;
                    *(float2*)&outF[(size_t)r * CC + cl] = make_float2(v0, v1);
                }
            }
        }

        // ---- agg for this block's 64 edges (efeat from smem stage st) ----
#pragma unroll
        for (int j = 0; j < 8; j++) {
            int r = wid * 8 + j;
            int e = row0 + r;
            if (e >= M) break;
            int s  = src[e];
            int d  = dst[e];
            int tt = etype[e];
            float alpha = escore[(size_t)e * HH + hh] / den[(size_t)d * HH + hh];
            // staged efeat fp16: row r, col group c4 = lane
            uint32_t off = SAS + (uint32_t)st * 16384u + (uint32_t)r * 256u
                + (uint32_t)((((lane >> 1) ^ (r & 7)) << 4) + ((lane & 1) << 3));
            uint2 eraw = *(uint2*)(smem + off);
            float2 e01 = __half22float2(*reinterpret_cast<__half2*>(&eraw.x));
            float2 e23 = __half22float2(*reinterpret_cast<__half2*>(&eraw.y));
            uint2 vraw = *(const uint2*)&vt[((size_t)tt * Nn + s) * CC + lane * 4];
            float2 v01 = __half22float2(*reinterpret_cast<__half2*>(&vraw.x));
            float2 v23 = __half22float2(*reinterpret_cast<__half2*>(&vraw.y));
            float m0 = (v01.x - e01.x) * alpha;
            float m1 = (v01.y - e01.y) * alpha;
            float m2 = (v23.x - e23.x) * alpha;
            float m3 = (v23.y - e23.y) * alpha;
            float* p = &wv[(size_t)d * CC + lane * 4];
            asm volatile("red.global.add.v4.f32 [%0], {%1, %2, %3, %4};"
                         :: "l"(p), "f"(m0), "f"(m1), "f"(m2), "f"(m3) : "memory");
        }
    }
#undef LDG_BLK
#undef STS_BLK
}

// =====================================================================================
// R12 GEMM (kept for W2: fp16 A, K = 512)
// =====================================================================================
#define NSTG 4
#define SA 0
#define SB 4096
#define STG 12288
#define SM_TOTAL 49152

__global__ void __launch_bounds__(256, 3) gemm_fp16_kernel(
    const __half* __restrict__ Ah,
    int ldx, int kTot,
    const __half* __restrict__ Bh,
    int ldw,
    const float* __restrict__ bias,
    const float* __restrict__ res,
    float* __restrict__ outF, int ldo,
    int M)
{
    extern __shared__ char smem[];
    const uint32_t sb = smem_u32(smem);
    const int tid  = threadIdx.x;
    const int wid  = tid >> 5;
    const int lane = tid & 31;
    const int wm   = wid & 1;
    const int wn   = wid >> 1;
    const int row0 = blockIdx.x * 64;

    const int nCh = kTot >> 5;

    float acc[2][4][4];
#pragma unroll
    for (int i = 0; i < 2; i++)
#pragma unroll
        for (int j = 0; j < 4; j++)
#pragma unroll
            for (int l = 0; l < 4; l++) acc[i][j][l] = 0.0f;

#define PREFETCH_B(kc, st) do {                                                    \
        uint32_t base = sb + (uint32_t)(st) * STG;                                 \
        _Pragma("unroll")                                                          \
        for (int i = 0; i < 2; i++) {                                              \
            int u = tid + i * 256;                                                 \
            int kk = u >> 4, c16 = u & 15;                                         \
            size_t gsrc = (size_t)((kc) * 32 + kk) * ldw + c16 * 8;                \
            cp16(base + SB + b_swz(kk, c16), Bh + gsrc);                           \
        }                                                                          \
    } while (0)

#define PREFETCH_A16(kc, st) do {                                                  \
        uint32_t base = sb + (uint32_t)(st) * STG;                                 \
        {                                                                          \
            int u = tid;                                                           \
            int r = u >> 2, c16 = u & 3;                                           \
            int row = row0 + r;                                                    \
            size_t gsrc = (size_t)row * ldx + (kc) * 32 + c16 * 8;                 \
            int bytes = (row < M) ? 16 : 0;                                        \
            cp16z(base + SA + a_swz(r, c16), Ah + gsrc, bytes);                    \
        }                                                                          \
    } while (0)

#pragma unroll
    for (int c = 0; c < NSTG - 1; c++) {
        if (c < nCh) {
            PREFETCH_B(c, c);
            PREFETCH_A16(c, c);
        }
        cp_commit();
    }

    const int a_r  = wm * 32 + (lane & 15);
    const int a_k8 = (lane >> 4) << 3;
    const int b_k  = (((lane >> 3) & 1) << 3) + (lane & 7);
    const int b_n  = wn * 32 + ((lane >> 4) << 3);

    for (int kc = 0; kc < nCh; kc++) {
        const int s = kc & (NSTG - 1);
        const uint32_t base = sb + (uint32_t)s * STG;

        cp_wait2();
        __syncthreads();

        {
            int pf = kc + NSTG - 1;
            if (pf < nCh) {
                PREFETCH_B(pf, pf & (NSTG - 1));
                PREFETCH_A16(pf, pf & (NSTG - 1));
            }
            cp_commit();
        }

#pragma unroll
        for (int ks = 0; ks < 2; ks++) {
            const int k0 = ks * 16;
            uint32_t bh[4][2];
            {
                int kk = k0 + b_k;
#pragma unroll
                for (int pair = 0; pair < 2; pair++) {
                    int n = b_n + pair * 16;
                    uint32_t addr = (uint32_t)kk * 256u
                        + (((uint32_t)(n * 2)) ^ (uint32_t)((kk & 7) << 4));
                    uint32_t r[4];
                    ldsm_x4_t(r, base + SB + addr);
                    bh[2 * pair][0] = r[0]; bh[2 * pair][1] = r[1];
                    bh[2 * pair + 1][0] = r[2]; bh[2 * pair + 1][1] = r[3];
                }
            }
            uint32_t a[2][4];
            {
                int kk = k0 + a_k8;
#pragma unroll
                for (int mf = 0; mf < 2; mf++)
                    ldsm_x4(a[mf], base + SA + a_swz(a_r + mf * 16, kk >> 3));
            }
#pragma unroll
            for (int mf = 0; mf < 2; mf++)
#pragma unroll
                for (int nf = 0; nf < 4; nf++)
                    mma16816(acc[mf][nf], a[mf], bh[nf]);
        }
    }

    const int g = lane >> 2;
    const int t = lane & 3;
#pragma unroll
    for (int mf = 0; mf < 2; mf++) {
#pragma unroll
        for (int nf = 0; nf < 4; nf++) {
            int cl = wn * 32 + nf * 8 + 2 * t;
            float b0 = bias[cl], b1 = bias[cl + 1];
#pragma unroll
            for (int half = 0; half < 2; half++) {
                int r = row0 + wm * 32 + mf * 16 + g + half * 8;
                if (r >= M) continue;
                float v0 = acc[mf][nf][2 * half]     + b0;
                float v1 = acc[mf][nf][2 * half + 1] + b1;
                float2 rv = *(const float2*)&res[(size_t)r * 128 + cl];
                v0 += rv.x; v1 += rv.y;
                *(float2*)&outF[(size_t)r * ldo + cl] = make_float2(v0, v1);
            }
        }
    }
#undef PREFETCH_B
#undef PREFETCH_A16
}

// ---------------- weight conversion (once) -------------------------------------------
__global__ void conv_weights_kernel(
    const float* __restrict__ Wq, const float* __restrict__ Wk,
    const float* __restrict__ Wv, const float* __restrict__ Wrel,
    const float* __restrict__ Wproj, const float* __restrict__ Wew,
    const float* __restrict__ W1, const float* __restrict__ W2,
    const float* __restrict__ bq, const float* __restrict__ bk,
    const float* __restrict__ bv,
    __half* __restrict__ wh, float* __restrict__ bias_qkv)
{
    int i = blockIdx.x * blockDim.x + threadIdx.x;
    if (i < 3 * CC)
        bias_qkv[i] = (i < CC) ? bq[i] : (i < 2 * CC ? bk[i - CC] : bv[i - 2 * CC]);
    if (i >= WBF_TOTAL) return;
    float x;
    if (i < WOFF_K)           x = Wq[i];
    else if (i < WOFF_V)      x = Wk[i - WOFF_K];
    else if (i < WOFF_REL)    x = Wv[i - WOFF_V];
    else if (i < WOFF_PROJ)   x = Wrel[i - WOFF_REL];
    else if (i < WOFF_EW)     x = Wproj[i - WOFF_PROJ];
    else if (i < WOFF_W1)     x = Wew[i - WOFF_EW];
    else if (i < WOFF_W2)     x = W1[i - WOFF_W1];
    else                      x = W2[i - WOFF_W2];
    wh[i] = __float2half_rn(x);
}

// ---------------- fp32 -> fp16 + zero accumulators -------------------------------------
__global__ void prep_kernel(const float* __restrict__ x,
                            __half* __restrict__ h16, size_t n,
                            float* __restrict__ z1, size_t n1,
                            float* __restrict__ z2, size_t n2)
{
    size_t i = (size_t)blockIdx.x * blockDim.x + threadIdx.x;
    size_t stride = (size_t)gridDim.x * blockDim.x;
    for (size_t j = i; j < n; j += stride) h16[j] = __float2half_rn(x[j]);
    for (size_t j = i; j < n1; j += stride) z1[j] = 0.0f;
    for (size_t j = i; j < n2; j += stride) z2[j] = 0.0f;
}

// ---------------- edge scores (fp16 q,k gathers) + softmax denominators -----------------
__global__ void score_kernel(
    const __half* __restrict__ q, const __half* __restrict__ k,
    const int* __restrict__ src, const int* __restrict__ dst,
    float* __restrict__ escore, float* __restrict__ den, int E)
{
    long idx = (long)blockIdx.x * blockDim.x + threadIdx.x;
    if (idx >= (long)E * HH) return;
    int e = (int)(idx >> 3);
    int h = (int)(idx & 7);
    int s = src[e], d = dst[e];
    const uint4* qp = (const uint4*)&q[(size_t)d * CC + h * 16];
    const uint4* kp = (const uint4*)&k[(size_t)s * CC + h * 16];
    float acc = 0.f;
#pragma unroll
    for (int i = 0; i < 2; i++) {
        uint4 qa = qp[i], kb = kp[i];
        const uint32_t* qu = &qa.x;
        const uint32_t* ku = &kb.x;
#pragma unroll
        for (int j = 0; j < 4; j++) {
            float2 fq = __half22float2(*reinterpret_cast<const __half2*>(&qu[j]));
            float2 fk = __half22float2(*reinterpret_cast<const __half2*>(&ku[j]));
            acc += fq.x * fk.x + fq.y * fk.y;
        }
    }
    acc *= 0.25f;
    acc = fminf(fmaxf(acc, -10.0f), 10.0f);
    float ex = expf(acc);
    escore[idx] = ex;
    atomicAdd(&den[(size_t)d * HH + h], ex);
}

// ---------------- layernorm, emits fp16 --------------------------------------------------
__global__ void ln_kernel(
    const float* __restrict__ x, const float* __restrict__ g,
    const float* __restrict__ b, __half* __restrict__ oh, int M)
{
    int row = (int)(((long)blockIdx.x * blockDim.x + threadIdx.x) >> 5);
    if (row >= M) return;
    int lane = threadIdx.x & 31;
    float4 v = *(const float4*)&x[(size_t)row * CC + lane * 4];
    float s = v.x + v.y + v.z + v.w;
#pragma unroll
    for (int o = 16; o > 0; o >>= 1) s += __shfl_xor_sync(0xffffffffu, s, o);
    float mu = s * (1.0f / 128.0f);
    float d0 = v.x - mu, d1 = v.y - mu, d2 = v.z - mu, d3 = v.w - mu;
    float ss = d0 * d0 + d1 * d1 + d2 * d2 + d3 * d3;
#pragma unroll
    for (int o = 16; o > 0; o >>= 1) ss += __shfl_xor_sync(0xffffffffu, ss, o);
    float inv = rsqrtf(ss * (1.0f / 128.0f) + 1e-5f);
    float4 gg = *(const float4*)&g[lane * 4];
    float4 bb = *(const float4*)&b[lane * 4];
    __half2 h0 = __floats2half2_rn(d0 * inv * gg.x + bb.x, d1 * inv * gg.y + bb.y);
    __half2 h1 = __floats2half2_rn(d2 * inv * gg.z + bb.z, d3 * inv * gg.w + bb.w);
    size_t o = (size_t)row * CC + lane * 4;
    *(__half2*)&oh[o]     = h0;
    *(__half2*)&oh[o + 2] = h1;
}

// ---------------- host side ----------------------------------------------------------------
static __half* h_wh;

extern "C" void kernel_launch(void* const* d_in, const int* in_sizes, int n_in,
                              void* d_out, int out_size)
{
    const float* feat  = (const float*)d_in[0];
    const float* efeat = (const float*)d_in[1];
    const int*   src   = (const int*)d_in[2];
    const int*   dst   = (const int*)d_in[3];
    const int*   etype = (const int*)d_in[4];

    int base = 5;
    if (in_sizes[5] == 1) base = 6;

    const float* Wq    = (const float*)d_in[base + 0];
    const float* bq    = (const float*)d_in[base + 1];
    const float* Wk    = (const float*)d_in[base + 2];
    const float* bk    = (const float*)d_in[base + 3];
    const float* Wv    = (const float*)d_in[base + 4];
    const float* bv    = (const float*)d_in[base + 5];
    const float* W_rel = (const float*)d_in[base + 6];
    const float* Wproj = (const float*)d_in[base + 7];
    const float* bproj = (const float*)d_in[base + 8];
    const float* WeW   = (const float*)d_in[base + 9];
    const float* beW   = (const float*)d_in[base + 10];
    const float* ln_g  = (const float*)d_in[base + 11];
    const float* ln_b  = (const float*)d_in[base + 12];
    const float* W1    = (const float*)d_in[base + 13];
    const float* b1    = (const float*)d_in[base + 14];
    const float* W2    = (const float*)d_in[base + 15];
    const float* b2    = (const float*)d_in[base + 16];

    const int N = in_sizes[0] / CC;
    const int E = in_sizes[1] / CC;
    const int nBlkN = (N + 63) / 64;
    const int nBlkE = (E + 63) / 64;

    float *esc, *den, *wv, *feat1, *bias_qkv;
    __half *qkv16, *f16, *hn16, *vt16, *hmid16;
    cudaGetSymbolAddress((void**)&qkv16,   g_qkv16);
    cudaGetSymbolAddress((void**)&esc,     g_escore);
    cudaGetSymbolAddress((void**)&den,     g_den);
    cudaGetSymbolAddress((void**)&wv,      g_wv);
    cudaGetSymbolAddress((void**)&feat1,   g_feat1);
    cudaGetSymbolAddress((void**)&bias_qkv, g_bias_qkv);
    cudaGetSymbolAddress((void**)&f16,     g_feat16);
    cudaGetSymbolAddress((void**)&hn16,    g_hn16);
    cudaGetSymbolAddress((void**)&vt16,    g_vt16);
    cudaGetSymbolAddress((void**)&hmid16,  g_hmid16);
    cudaGetSymbolAddress((void**)&h_wh,    g_wh);

    cudaFuncSetAttribute(gemm_fp16_kernel,
                         cudaFuncAttributeMaxDynamicSharedMemorySize, SM_TOTAL);
    cudaFuncSetAttribute(gemm_stream_kernel,
                         cudaFuncAttributeMaxDynamicSharedMemorySize, SMS_TOTAL);
    cudaFuncSetAttribute(gemm_stream_f32_kernel,
                         cudaFuncAttributeMaxDynamicSharedMemorySize, SMS_TOTAL);
    cudaFuncSetAttribute(ew_agg_kernel,
                         cudaFuncAttributeMaxDynamicSharedMemorySize, SMS_TOTAL);

    float* out_feat  = (float*)d_out;
    float* out_efeat = (float*)d_out + (size_t)N * CC;
    __half* q16 = qkv16;
    __half* k16 = qkv16 + (size_t)N * CC;
    __half* v16 = qkv16 + (size_t)2 * N * CC;

    // 0) one-time prep
    conv_weights_kernel<<<(WBF_TOTAL + 255) / 256, 256>>>(
        Wq, Wk, Wv, W_rel, Wproj, WeW, W1, W2, bq, bk, bv, h_wh, bias_qkv);
    prep_kernel<<<1024, 256>>>(feat, f16, (size_t)N * CC,
                               den, (size_t)N * HH, wv, (size_t)N * CC);

    // 1) fused q+k+v (stream kernel, grid.y = 3, fp16 out)
    gemm_stream_kernel<<<dim3(148, 3), 256, SMS_TOTAL>>>(
        f16, CC, h_wh + WOFF_Q, CC, 16384, 0,
        bias_qkv, CC,
        nullptr, CC, (size_t)N * CC,
        qkv16, 2, N, 0, nBlkN);

    // 2) vt16[t] = v16 @ W_rel[t] (stream kernel, grid.y = 8, fp16 out)
    gemm_stream_kernel<<<dim3(56, TT), 256, SMS_TOTAL>>>(
        v16, CC, h_wh + WOFF_REL, CC, 16384, 0,
        nullptr, 0,
        nullptr, CC, (size_t)N * CC,
        vt16, 2, N, 0, nBlkN);

    // 3) edge scores + denominators
    {
        long total = (long)E * HH;
        score_kernel<<<(int)((total + 255) / 256), 256>>>(q16, k16, src, dst, esc, den, E);
    }

    // 4) FUSED: efeat_out = efeat @ WeW + beW  AND  wv += alpha*(vt - efeat)
    ew_agg_kernel<<<296, 256, SMS_TOTAL>>>(
        efeat, h_wh + WOFF_EW, CC, beW, out_efeat,
        vt16, esc, den, src, dst, etype, wv, N, E, nBlkE);

    // 5) feat1 = feat + wv @ Wproj + bproj  (fp32-A stream)
    gemm_stream_f32_kernel<<<296, 256, SMS_TOTAL>>>(
        wv, CC, h_wh + WOFF_PROJ, CC, bproj, feat, feat1, CC, N, nBlkN);

    // 6) hn = layernorm(feat1) -> fp16
    {
        long total = (long)N * 32;
        ln_kernel<<<(int)((total + 255) / 256), 256>>>(feat1, ln_g, ln_b, hn16, N);
    }

    // 7) hmid16 = gelu(hn @ W1 + b1)  (stream kernel, grid.y = 4, fp16 out)
    gemm_stream_kernel<<<dim3(111, 4), 256, SMS_TOTAL>>>(
        hn16, CC, h_wh + WOFF_W1, 4 * CC, 0, 128,
        b1, 0,
        nullptr, 4 * CC, 0,
        hmid16, 2, N, 1, nBlkN);

    // 8) feat_out = feat1 + hmid16 @ W2 + b2  (fp16 A, K = 512, R12 kernel)
    gemm_fp16_kernel<<<dim3(nBlkN, 1), 256, SM_TOTAL>>>(
        hmid16, 4 * CC, 4 * CC, h_wh + WOFF_W2, CC,
        b2, feat1, out_feat, CC, N);
}

// round 17
// speedup vs baseline: 1.3370x; 1.3370x over previous
#include <cuda_runtime.h>
#include <cuda_fp16.h>
#include <math.h>
#include <stdint.h>

// Problem constants
#define NN 50000
#define EE 800000
#define CC 128
#define HH 8
#define TT 8

// ---------------- scratch (device globals) -------------------------------------
__device__ __half g_qkv16[(size_t)3 * NN * CC];      // q16, k16, v16 contiguous
__device__ __half g_feat16[(size_t)NN * CC];
__device__ __half g_hn16[(size_t)NN * CC];
__device__ __half g_vt16[(size_t)TT * NN * CC];
__device__ __half g_hmid16[(size_t)NN * 4 * CC];
__device__ float g_escore[(size_t)EE * HH];
__device__ float g_den[(size_t)NN * HH];
__device__ float g_wv[(size_t)NN * CC];
__device__ float g_feat1[(size_t)NN * CC];
__device__ float g_bias_qkv[3 * CC];

// fp16 weights
#define WOFF_Q    0
#define WOFF_K    16384
#define WOFF_V    32768
#define WOFF_REL  49152
#define WOFF_PROJ 180224
#define WOFF_EW   196608
#define WOFF_W1   212992
#define WOFF_W2   278528
#define WBF_TOTAL 344064
__device__ __half g_wh[WBF_TOTAL];

// ---------------- helpers -----------------------------------------------------------
__device__ __forceinline__ uint32_t half2_u(__half2 v) {
    return *reinterpret_cast<uint32_t*>(&v);
}
__device__ __forceinline__ uint32_t smem_u32(const void* p) {
    uint32_t addr;
    asm("{ .reg .u64 t; cvta.to.shared.u64 t, %1; cvt.u32.u64 %0, t; }"
        : "=r"(addr) : "l"(p));
    return addr;
}
__device__ __forceinline__ void ldsm_x4(uint32_t* r, uint32_t addr) {
    asm volatile("ldmatrix.sync.aligned.m8n8.x4.shared.b16 {%0,%1,%2,%3}, [%4];"
                 : "=r"(r[0]), "=r"(r[1]), "=r"(r[2]), "=r"(r[3]) : "r"(addr));
}
__device__ __forceinline__ void ldsm_x4_t(uint32_t* r, uint32_t addr) {
    asm volatile("ldmatrix.sync.aligned.m8n8.x4.trans.shared.b16 {%0,%1,%2,%3}, [%4];"
                 : "=r"(r[0]), "=r"(r[1]), "=r"(r[2]), "=r"(r[3]) : "r"(addr));
}
__device__ __forceinline__ void mma16816(float* c, const uint32_t* a, const uint32_t* b) {
    asm volatile(
        "mma.sync.aligned.m16n8k16.row.col.f32.f16.f16.f32 "
        "{%0,%1,%2,%3}, {%4,%5,%6,%7}, {%8,%9}, {%0,%1,%2,%3};"
        : "+f"(c[0]), "+f"(c[1]), "+f"(c[2]), "+f"(c[3])
        : "r"(a[0]), "r"(a[1]), "r"(a[2]), "r"(a[3]), "r"(b[0]), "r"(b[1]));
}
__device__ __forceinline__ void cp16(uint32_t dst, const void* src) {
    asm volatile("cp.async.cg.shared.global [%0], [%1], 16;"
                 :: "r"(dst), "l"(src) : "memory");
}
__device__ __forceinline__ void cp16z(uint32_t dst, const void* src, int bytes) {
    asm volatile("cp.async.cg.shared.global [%0], [%1], 16, %2;"
                 :: "r"(dst), "l"(src), "r"(bytes) : "memory");
}
__device__ __forceinline__ void cp_commit() {
    asm volatile("cp.async.commit_group;" ::: "memory");
}
__device__ __forceinline__ void cp_wait0() {
    asm volatile("cp.async.wait_group 0;" ::: "memory");
}
__device__ __forceinline__ void cp_wait2() {
    asm volatile("cp.async.wait_group 2;" ::: "memory");
}

__device__ __forceinline__ uint32_t a_swz(int r, int c16) {
    return (uint32_t)r * 64u + (uint32_t)((c16 ^ ((r >> 1) & 3)) << 4);
}
__device__ __forceinline__ uint32_t b_swz(int k, int c16) {
    return (uint32_t)k * 256u + (uint32_t)((c16 ^ (k & 7)) << 4);
}
__device__ __forceinline__ float gelu1(float v) {
    return 0.5f * v * (1.0f + erff(v * 0.70710678118654752f));
}

// =====================================================================================
// STREAM GEMM (fp16 A, K = 128): B (128x128 fp16, 32KB) resident in smem, and its
// fragments hoisted into REGISTERS once (64 regs) — mainloop has only A-ldsm + MMA.
// Persistent CTAs loop over 64-row blocks; A double-buffered (2 x 16KB).
// =====================================================================================
#define SBS 0
#define SAS 32768
#define SMS_TOTAL 65536

__global__ void __launch_bounds__(256, 2) gemm_stream_kernel(
    const __half* __restrict__ Ah, int ldx,
    const __half* __restrict__ Bh, int ldw, size_t w_y_off, int col_y,
    const float* __restrict__ bias, int bias_y_off,
    float* __restrict__ outF, int ldo, size_t out_y_off,
    __half* __restrict__ outH, int halfMode,
    int M, int doGelu, int nBlk)
{
    extern __shared__ char smem[];
    const uint32_t sb = smem_u32(smem);
    const int tid  = threadIdx.x;
    const int wid  = tid >> 5;
    const int lane = tid & 31;
    const int wm   = wid & 1;
    const int wn   = wid >> 1;
    const int wcol0 = blockIdx.y * col_y;

    Bh += (size_t)blockIdx.y * w_y_off;
    if (outF) outF += (size_t)blockIdx.y * out_y_off;
    if (halfMode == 2 && outH) outH += (size_t)blockIdx.y * out_y_off;
    if (bias) bias += (size_t)blockIdx.y * bias_y_off;

#pragma unroll
    for (int i = 0; i < 8; i++) {
        int idx = tid + i * 256;
        int kk = idx >> 4, c16 = idx & 15;
        cp16(sb + SBS + (uint32_t)kk * 256u + (uint32_t)((c16 ^ (kk & 7)) << 4),
             Bh + (size_t)kk * ldw + wcol0 + c16 * 8);
    }
    cp_commit();

#define PREF_A(blk, st) do {                                                       \
        uint32_t base = sb + SAS + (uint32_t)(st) * 16384u;                        \
        _Pragma("unroll")                                                          \
        for (int i = 0; i < 4; i++) {                                              \
            int idx = tid + i * 256;                                               \
            int r = idx >> 4, c16 = idx & 15;                                      \
            int row = (blk) * 64 + r;                                              \
            int bytes = (row < M) ? 16 : 0;                                        \
            cp16z(base + (uint32_t)r * 256u + (uint32_t)((c16 ^ (r & 7)) << 4),    \
                  Ah + (size_t)row * ldx + c16 * 8, bytes);                        \
        }                                                                          \
    } while (0)

    PREF_A(blockIdx.x, 0);
    cp_commit();

    const int a_r  = wm * 32 + (lane & 15);
    const int a_k8 = (lane >> 4) << 3;
    const int b_k  = (((lane >> 3) & 1) << 3) + (lane & 7);
    const int b_n  = wn * 32 + ((lane >> 4) << 3);
    const int g = lane >> 2;
    const int t = lane & 3;
    const bool h16 = (halfMode == 2);

    // wait for B + first A stage; then hoist all B fragments into registers
    cp_wait0();
    __syncthreads();

    uint32_t breg[8][4][2];
#pragma unroll
    for (int ks = 0; ks < 8; ks++) {
        const int kk = ks * 16 + b_k;
#pragma unroll
        for (int pair = 0; pair < 2; pair++) {
            int n = b_n + pair * 16;
            uint32_t addr = (uint32_t)kk * 256u
                + (((uint32_t)(n * 2)) ^ (uint32_t)((kk & 7) << 4));
            uint32_t r[4];
            ldsm_x4_t(r, sb + SBS + addr);
            breg[ks][2 * pair][0] = r[0];     breg[ks][2 * pair][1] = r[1];
            breg[ks][2 * pair + 1][0] = r[2]; breg[ks][2 * pair + 1][1] = r[3];
        }
    }

    int iter = 0;
    for (int blk = blockIdx.x; blk < nBlk; blk += gridDim.x, iter++) {
        const int st = iter & 1;
        const uint32_t abase = sb + SAS + (uint32_t)st * 16384u;

        if (iter > 0) {
            cp_wait0();
            __syncthreads();      // A(st) landed and visible to all threads
        }

        int nxt = blk + gridDim.x;
        if (nxt < nBlk) PREF_A(nxt, st ^ 1);
        cp_commit();

        float acc[2][4][4];
#pragma unroll
        for (int i = 0; i < 2; i++)
#pragma unroll
            for (int j = 0; j < 4; j++)
#pragma unroll
                for (int l = 0; l < 4; l++) acc[i][j][l] = 0.0f;

#pragma unroll
        for (int ks = 0; ks < 8; ks++) {
            uint32_t a[2][4];
            {
                int kk = ks * 16 + a_k8;
#pragma unroll
                for (int mf = 0; mf < 2; mf++) {
                    int r = a_r + mf * 16;
                    uint32_t addr = (uint32_t)r * 256u
                        + (((uint32_t)(kk * 2)) ^ (uint32_t)((r & 7) << 4));
                    ldsm_x4(a[mf], abase + addr);
                }
            }
#pragma unroll
            for (int mf = 0; mf < 2; mf++)
#pragma unroll
                for (int nf = 0; nf < 4; nf++)
                    mma16816(acc[mf][nf], a[mf], breg[ks][nf]);
        }
        __syncthreads();          // all reads of A(st) done before it is refilled

        const int row0 = blk * 64;
#pragma unroll
        for (int mf = 0; mf < 2; mf++) {
#pragma unroll
            for (int nf = 0; nf < 4; nf++) {
                int cl = wn * 32 + nf * 8 + 2 * t;
                float b0 = 0.f, b1 = 0.f;
                if (bias) { b0 = bias[wcol0 + cl]; b1 = bias[wcol0 + cl + 1]; }
#pragma unroll
                for (int half = 0; half < 2; half++) {
                    int r = row0 + wm * 32 + mf * 16 + g + half * 8;
                    if (r >= M) continue;
                    float v0 = acc[mf][nf][2 * half]     + b0;
                    float v1 = acc[mf][nf][2 * half + 1] + b1;
                    if (doGelu) { v0 = gelu1(v0); v1 = gelu1(v1); }
                    if (h16) {
                        *(__half2*)&outH[(size_t)r * ldo + wcol0 + cl]
                            = __floats2half2_rn(v0, v1);
                    } else {
                        *(float2*)&outF[(size_t)r * ldo + wcol0 + cl]
                            = make_float2(v0, v1);
                    }
                }
            }
        }
    }
#undef PREF_A
}

// =====================================================================================
// STREAM GEMM fp32 A (K = 128), B resident. For proj (res supported) and ew.
// =====================================================================================
__global__ void __launch_bounds__(256, 2) gemm_stream_f32_kernel(
    const float* __restrict__ Xf, int ldx,
    const __half* __restrict__ Bh, int ldw,
    const float* __restrict__ bias,
    const float* __restrict__ res,
    float* __restrict__ outF, int ldo,
    int M, int nBlk)
{
    extern __shared__ char smem[];
    const uint32_t sb = smem_u32(smem);
    const int tid  = threadIdx.x;
    const int wid  = tid >> 5;
    const int lane = tid & 31;
    const int wm   = wid & 1;
    const int wn   = wid >> 1;

#pragma unroll
    for (int i = 0; i < 8; i++) {
        int idx = tid + i * 256;
        int kk = idx >> 4, c16 = idx & 15;
        cp16(sb + SBS + (uint32_t)kk * 256u + (uint32_t)((c16 ^ (kk & 7)) << 4),
             Bh + (size_t)kk * ldw + c16 * 8);
    }
    cp_commit();

    float4 ap[8];

#define LDG_BLK(blk) do {                                                          \
        _Pragma("unroll")                                                          \
        for (int i = 0; i < 8; i++) {                                              \
            int idx = tid + i * 256;                                               \
            int r = idx >> 5, c4 = idx & 31;                                       \
            int row = (blk) * 64 + r;                                              \
            ap[i] = (row < M)                                                      \
                ? *(const float4*)&Xf[(size_t)row * ldx + c4 * 4]                  \
                : make_float4(0.f, 0.f, 0.f, 0.f);                                 \
        }                                                                          \
    } while (0)

#define STS_BLK(st) do {                                                           \
        uint32_t base = SAS + (uint32_t)(st) * 16384u;                             \
        _Pragma("unroll")                                                          \
        for (int i = 0; i < 8; i++) {                                              \
            int idx = tid + i * 256;                                               \
            int r = idx >> 5, c4 = idx & 31;                                       \
            __half2 h0 = __floats2half2_rn(ap[i].x, ap[i].y);                      \
            __half2 h1 = __floats2half2_rn(ap[i].z, ap[i].w);                      \
            uint32_t off = base + (uint32_t)r * 256u                               \
                + (uint32_t)((((c4 >> 1) ^ (r & 7)) << 4) + ((c4 & 1) << 3));      \
            *(uint2*)(smem + off) = make_uint2(half2_u(h0), half2_u(h1));          \
        }                                                                          \
    } while (0)

    LDG_BLK(blockIdx.x);
    cp_wait0();

    const int a_r  = wm * 32 + (lane & 15);
    const int a_k8 = (lane >> 4) << 3;
    const int b_k  = (((lane >> 3) & 1) << 3) + (lane & 7);
    const int b_n  = wn * 32 + ((lane >> 4) << 3);
    const int g = lane >> 2;
    const int t = lane & 3;

    int iter = 0;
    for (int blk = blockIdx.x; blk < nBlk; blk += gridDim.x, iter++) {
        const int st = iter & 1;
        const uint32_t abase = sb + SAS + (uint32_t)st * 16384u;

        STS_BLK(st);
        __syncthreads();

        int nxt = blk + gridDim.x;
        if (nxt < nBlk) LDG_BLK(nxt);

        float acc[2][4][4];
#pragma unroll
        for (int i = 0; i < 2; i++)
#pragma unroll
            for (int j = 0; j < 4; j++)
#pragma unroll
                for (int l = 0; l < 4; l++) acc[i][j][l] = 0.0f;

#pragma unroll
        for (int ks = 0; ks < 8; ks++) {
            const int k0 = ks * 16;
            uint32_t bh[4][2];
            {
                int kk = k0 + b_k;
#pragma unroll
                for (int pair = 0; pair < 2; pair++) {
                    int n = b_n + pair * 16;
                    uint32_t addr = (uint32_t)kk * 256u
                        + (((uint32_t)(n * 2)) ^ (uint32_t)((kk & 7) << 4));
                    uint32_t r[4];
                    ldsm_x4_t(r, sb + SBS + addr);
                    bh[2 * pair][0] = r[0]; bh[2 * pair][1] = r[1];
                    bh[2 * pair + 1][0] = r[2]; bh[2 * pair + 1][1] = r[3];
                }
            }
            uint32_t a[2][4];
            {
                int kk = k0 + a_k8;
#pragma unroll
                for (int mf = 0; mf < 2; mf++) {
                    int r = a_r + mf * 16;
                    uint32_t addr = (uint32_t)r * 256u
                        + (((uint32_t)(kk * 2)) ^ (uint32_t)((r & 7) << 4));
                    ldsm_x4(a[mf], abase + addr);
                }
            }
#pragma unroll
            for (int mf = 0; mf < 2; mf++)
#pragma unroll
                for (int nf = 0; nf < 4; nf++)
                    mma16816(acc[mf][nf], a[mf], bh[nf]);
        }

        const int row0 = blk * 64;
#pragma unroll
        for (int mf = 0; mf < 2; mf++) {
#pragma unroll
            for (int nf = 0; nf < 4; nf++) {
                int cl = wn * 32 + nf * 8 + 2 * t;
                float b0 = 0.f, b1 = 0.f;
                if (bias) { b0 = bias[cl]; b1 = bias[cl + 1]; }
#pragma unroll
                for (int half = 0; half < 2; half++) {
                    int r = row0 + wm * 32 + mf * 16 + g + half * 8;
                    if (r >= M) continue;
                    float v0 = acc[mf][nf][2 * half]     + b0;
                    float v1 = acc[mf][nf][2 * half + 1] + b1;
                    if (res) {
                        float2 rv = *(const float2*)&res[(size_t)r * 128 + cl];
                        v0 += rv.x; v1 += rv.y;
                    }
                    *(float2*)&outF[(size_t)r * ldo + cl] = make_float2(v0, v1);
                }
            }
        }
    }
#undef LDG_BLK
#undef STS_BLK
}

// =====================================================================================
// R12 GEMM (kept for W2: fp16 A, K = 512)
// =====================================================================================
#define NSTG 4
#define SA 0
#define SB 4096
#define STG 12288
#define SM_TOTAL 49152

__global__ void __launch_bounds__(256, 3) gemm_fp16_kernel(
    const __half* __restrict__ Ah,
    int ldx, int kTot,
    const __half* __restrict__ Bh,
    int ldw,
    const float* __restrict__ bias,
    const float* __restrict__ res,
    float* __restrict__ outF, int ldo,
    int M)
{
    extern __shared__ char smem[];
    const uint32_t sb = smem_u32(smem);
    const int tid  = threadIdx.x;
    const int wid  = tid >> 5;
    const int lane = tid & 31;
    const int wm   = wid & 1;
    const int wn   = wid >> 1;
    const int row0 = blockIdx.x * 64;

    const int nCh = kTot >> 5;

    float acc[2][4][4];
#pragma unroll
    for (int i = 0; i < 2; i++)
#pragma unroll
        for (int j = 0; j < 4; j++)
#pragma unroll
            for (int l = 0; l < 4; l++) acc[i][j][l] = 0.0f;

#define PREFETCH_B(kc, st) do {                                                    \
        uint32_t base = sb + (uint32_t)(st) * STG;                                 \
        _Pragma("unroll")                                                          \
        for (int i = 0; i < 2; i++) {                                              \
            int u = tid + i * 256;                                                 \
            int kk = u >> 4, c16 = u & 15;                                         \
            size_t gsrc = (size_t)((kc) * 32 + kk) * ldw + c16 * 8;                \
            cp16(base + SB + b_swz(kk, c16), Bh + gsrc);                           \
        }                                                                          \
    } while (0)

#define PREFETCH_A16(kc, st) do {                                                  \
        uint32_t base = sb + (uint32_t)(st) * STG;                                 \
        {                                                                          \
            int u = tid;                                                           \
            int r = u >> 2, c16 = u & 3;                                           \
            int row = row0 + r;                                                    \
            size_t gsrc = (size_t)row * ldx + (kc) * 32 + c16 * 8;                 \
            int bytes = (row < M) ? 16 : 0;                                        \
            cp16z(base + SA + a_swz(r, c16), Ah + gsrc, bytes);                    \
        }                                                                          \
    } while (0)

#pragma unroll
    for (int c = 0; c < NSTG - 1; c++) {
        if (c < nCh) {
            PREFETCH_B(c, c);
            PREFETCH_A16(c, c);
        }
        cp_commit();
    }

    const int a_r  = wm * 32 + (lane & 15);
    const int a_k8 = (lane >> 4) << 3;
    const int b_k  = (((lane >> 3) & 1) << 3) + (lane & 7);
    const int b_n  = wn * 32 + ((lane >> 4) << 3);

    for (int kc = 0; kc < nCh; kc++) {
        const int s = kc & (NSTG - 1);
        const uint32_t base = sb + (uint32_t)s * STG;

        cp_wait2();
        __syncthreads();

        {
            int pf = kc + NSTG - 1;
            if (pf < nCh) {
                PREFETCH_B(pf, pf & (NSTG - 1));
                PREFETCH_A16(pf, pf & (NSTG - 1));
            }
            cp_commit();
        }

#pragma unroll
        for (int ks = 0; ks < 2; ks++) {
            const int k0 = ks * 16;
            uint32_t bh[4][2];
            {
                int kk = k0 + b_k;
#pragma unroll
                for (int pair = 0; pair < 2; pair++) {
                    int n = b_n + pair * 16;
                    uint32_t addr = (uint32_t)kk * 256u
                        + (((uint32_t)(n * 2)) ^ (uint32_t)((kk & 7) << 4));
                    uint32_t r[4];
                    ldsm_x4_t(r, base + SB + addr);
                    bh[2 * pair][0] = r[0]; bh[2 * pair][1] = r[1];
                    bh[2 * pair + 1][0] = r[2]; bh[2 * pair + 1][1] = r[3];
                }
            }
            uint32_t a[2][4];
            {
                int kk = k0 + a_k8;
#pragma unroll
                for (int mf = 0; mf < 2; mf++)
                    ldsm_x4(a[mf], base + SA + a_swz(a_r + mf * 16, kk >> 3));
            }
#pragma unroll
            for (int mf = 0; mf < 2; mf++)
#pragma unroll
                for (int nf = 0; nf < 4; nf++)
                    mma16816(acc[mf][nf], a[mf], bh[nf]);
        }
    }

    const int g = lane >> 2;
    const int t = lane & 3;
#pragma unroll
    for (int mf = 0; mf < 2; mf++) {
#pragma unroll
        for (int nf = 0; nf < 4; nf++) {
            int cl = wn * 32 + nf * 8 + 2 * t;
            float b0 = bias[cl], b1 = bias[cl + 1];
#pragma unroll
            for (int half = 0; half < 2; half++) {
                int r = row0 + wm * 32 + mf * 16 + g + half * 8;
                if (r >= M) continue;
                float v0 = acc[mf][nf][2 * half]     + b0;
                float v1 = acc[mf][nf][2 * half + 1] + b1;
                float2 rv = *(const float2*)&res[(size_t)r * 128 + cl];
                v0 += rv.x; v1 += rv.y;
                *(float2*)&outF[(size_t)r * ldo + cl] = make_float2(v0, v1);
            }
        }
    }
#undef PREFETCH_B
#undef PREFETCH_A16
}

// ---------------- weight conversion (once) -------------------------------------------
__global__ void conv_weights_kernel(
    const float* __restrict__ Wq, const float* __restrict__ Wk,
    const float* __restrict__ Wv, const float* __restrict__ Wrel,
    const float* __restrict__ Wproj, const float* __restrict__ Wew,
    const float* __restrict__ W1, const float* __restrict__ W2,
    const float* __restrict__ bq, const float* __restrict__ bk,
    const float* __restrict__ bv,
    __half* __restrict__ wh, float* __restrict__ bias_qkv)
{
    int i = blockIdx.x * blockDim.x + threadIdx.x;
    if (i < 3 * CC)
        bias_qkv[i] = (i < CC) ? bq[i] : (i < 2 * CC ? bk[i - CC] : bv[i - 2 * CC]);
    if (i >= WBF_TOTAL) return;
    float x;
    if (i < WOFF_K)           x = Wq[i];
    else if (i < WOFF_V)      x = Wk[i - WOFF_K];
    else if (i < WOFF_REL)    x = Wv[i - WOFF_V];
    else if (i < WOFF_PROJ)   x = Wrel[i - WOFF_REL];
    else if (i < WOFF_EW)     x = Wproj[i - WOFF_PROJ];
    else if (i < WOFF_W1)     x = Wew[i - WOFF_EW];
    else if (i < WOFF_W2)     x = W1[i - WOFF_W1];
    else                      x = W2[i - WOFF_W2];
    wh[i] = __float2half_rn(x);
}

// ---------------- fp32 -> fp16 + zero accumulators -------------------------------------
__global__ void prep_kernel(const float* __restrict__ x,
                            __half* __restrict__ h16, size_t n,
                            float* __restrict__ z1, size_t n1,
                            float* __restrict__ z2, size_t n2)
{
    size_t i = (size_t)blockIdx.x * blockDim.x + threadIdx.x;
    size_t stride = (size_t)gridDim.x * blockDim.x;
    for (size_t j = i; j < n; j += stride) h16[j] = __float2half_rn(x[j]);
    for (size_t j = i; j < n1; j += stride) z1[j] = 0.0f;
    for (size_t j = i; j < n2; j += stride) z2[j] = 0.0f;
}

// ---------------- edge scores (fp16 q,k gathers) + softmax denominators -----------------
__global__ void score_kernel(
    const __half* __restrict__ q, const __half* __restrict__ k,
    const int* __restrict__ src, const int* __restrict__ dst,
    float* __restrict__ escore, float* __restrict__ den, int E)
{
    long idx = (long)blockIdx.x * blockDim.x + threadIdx.x;
    if (idx >= (long)E * HH) return;
    int e = (int)(idx >> 3);
    int h = (int)(idx & 7);
    int s = src[e], d = dst[e];
    const uint4* qp = (const uint4*)&q[(size_t)d * CC + h * 16];
    const uint4* kp = (const uint4*)&k[(size_t)s * CC + h * 16];
    float acc = 0.f;
#pragma unroll
    for (int i = 0; i < 2; i++) {
        uint4 qa = qp[i], kb = kp[i];
        const uint32_t* qu = &qa.x;
        const uint32_t* ku = &kb.x;
#pragma unroll
        for (int j = 0; j < 4; j++) {
            float2 fq = __half22float2(*reinterpret_cast<const __half2*>(&qu[j]));
            float2 fk = __half22float2(*reinterpret_cast<const __half2*>(&ku[j]));
            acc += fq.x * fk.x + fq.y * fk.y;
        }
    }
    acc *= 0.25f;
    acc = fminf(fmaxf(acc, -10.0f), 10.0f);
    float ex = expf(acc);
    escore[idx] = ex;
    atomicAdd(&den[(size_t)d * HH + h], ex);
}

// ---------------- edge aggregation: 2 edges per warp -------------------------------------
__global__ void agg_kernel(
    const __half* __restrict__ vt, const float* __restrict__ efeat,
    const float* __restrict__ escore, const float* __restrict__ den,
    const int* __restrict__ src, const int* __restrict__ dst,
    const int* __restrict__ etype,
    float* __restrict__ wv, int E, int Nn)
{
    long warpId = ((long)blockIdx.x * blockDim.x + threadIdx.x) >> 5;
    int lane = threadIdx.x & 31;
    int e = (int)(warpId * 2 + (lane >> 4));
    if (e >= E) return;
    int l = lane & 15;
    int s = src[e], d = dst[e], t = etype[e];
    int h = l >> 1;
    float alpha = escore[(size_t)e * HH + h] / den[(size_t)d * HH + h];

    uint4 raw = *(const uint4*)&vt[((size_t)t * Nn + s) * CC + l * 8];
    const uint32_t* vu = &raw.x;
    const float4* efp = (const float4*)&efeat[(size_t)e * CC + l * 8];
    float4 ef0 = efp[0], ef1 = efp[1];

    float2 f0 = __half22float2(*reinterpret_cast<const __half2*>(&vu[0]));
    float2 f1 = __half22float2(*reinterpret_cast<const __half2*>(&vu[1]));
    float2 f2 = __half22float2(*reinterpret_cast<const __half2*>(&vu[2]));
    float2 f3 = __half22float2(*reinterpret_cast<const __half2*>(&vu[3]));

    float m0 = (f0.x - ef0.x) * alpha;
    float m1 = (f0.y - ef0.y) * alpha;
    float m2 = (f1.x - ef0.z) * alpha;
    float m3 = (f1.y - ef0.w) * alpha;
    float m4 = (f2.x - ef1.x) * alpha;
    float m5 = (f2.y - ef1.y) * alpha;
    float m6 = (f3.x - ef1.z) * alpha;
    float m7 = (f3.y - ef1.w) * alpha;

    float* p = &wv[(size_t)d * CC + l * 8];
    asm volatile("red.global.add.v4.f32 [%0], {%1, %2, %3, %4};"
                 :: "l"(p), "f"(m0), "f"(m1), "f"(m2), "f"(m3) : "memory");
    asm volatile("red.global.add.v4.f32 [%0], {%1, %2, %3, %4};"
                 :: "l"(p + 4), "f"(m4), "f"(m5), "f"(m6), "f"(m7) : "memory");
}

// ---------------- layernorm, emits fp16 --------------------------------------------------
__global__ void ln_kernel(
    const float* __restrict__ x, const float* __restrict__ g,
    const float* __restrict__ b, __half* __restrict__ oh, int M)
{
    int row = (int)(((long)blockIdx.x * blockDim.x + threadIdx.x) >> 5);
    if (row >= M) return;
    int lane = threadIdx.x & 31;
    float4 v = *(const float4*)&x[(size_t)row * CC + lane * 4];
    float s = v.x + v.y + v.z + v.w;
#pragma unroll
    for (int o = 16; o > 0; o >>= 1) s += __shfl_xor_sync(0xffffffffu, s, o);
    float mu = s * (1.0f / 128.0f);
    float d0 = v.x - mu, d1 = v.y - mu, d2 = v.z - mu, d3 = v.w - mu;
    float ss = d0 * d0 + d1 * d1 + d2 * d2 + d3 * d3;
#pragma unroll
    for (int o = 16; o > 0; o >>= 1) ss += __shfl_xor_sync(0xffffffffu, ss, o);
    float inv = rsqrtf(ss * (1.0f / 128.0f) + 1e-5f);
    float4 gg = *(const float4*)&g[lane * 4];
    float4 bb = *(const float4*)&b[lane * 4];
    __half2 h0 = __floats2half2_rn(d0 * inv * gg.x + bb.x, d1 * inv * gg.y + bb.y);
    __half2 h1 = __floats2half2_rn(d2 * inv * gg.z + bb.z, d3 * inv * gg.w + bb.w);
    size_t o = (size_t)row * CC + lane * 4;
    *(__half2*)&oh[o]     = h0;
    *(__half2*)&oh[o + 2] = h1;
}

// ---------------- host side ----------------------------------------------------------------
static __half* h_wh;

extern "C" void kernel_launch(void* const* d_in, const int* in_sizes, int n_in,
                              void* d_out, int out_size)
{
    const float* feat  = (const float*)d_in[0];
    const float* efeat = (const float*)d_in[1];
    const int*   src   = (const int*)d_in[2];
    const int*   dst   = (const int*)d_in[3];
    const int*   etype = (const int*)d_in[4];

    int base = 5;
    if (in_sizes[5] == 1) base = 6;

    const float* Wq    = (const float*)d_in[base + 0];
    const float* bq    = (const float*)d_in[base + 1];
    const float* Wk    = (const float*)d_in[base + 2];
    const float* bk    = (const float*)d_in[base + 3];
    const float* Wv    = (const float*)d_in[base + 4];
    const float* bv    = (const float*)d_in[base + 5];
    const float* W_rel = (const float*)d_in[base + 6];
    const float* Wproj = (const float*)d_in[base + 7];
    const float* bproj = (const float*)d_in[base + 8];
    const float* WeW   = (const float*)d_in[base + 9];
    const float* beW   = (const float*)d_in[base + 10];
    const float* ln_g  = (const float*)d_in[base + 11];
    const float* ln_b  = (const float*)d_in[base + 12];
    const float* W1    = (const float*)d_in[base + 13];
    const float* b1    = (const float*)d_in[base + 14];
    const float* W2    = (const float*)d_in[base + 15];
    const float* b2    = (const float*)d_in[base + 16];

    const int N = in_sizes[0] / CC;
    const int E = in_sizes[1] / CC;
    const int nBlkN = (N + 63) / 64;
    const int nBlkE = (E + 63) / 64;

    float *esc, *den, *wv, *feat1, *bias_qkv;
    __half *qkv16, *f16, *hn16, *vt16, *hmid16;
    cudaGetSymbolAddress((void**)&qkv16,   g_qkv16);
    cudaGetSymbolAddress((void**)&esc,     g_escore);
    cudaGetSymbolAddress((void**)&den,     g_den);
    cudaGetSymbolAddress((void**)&wv,      g_wv);
    cudaGetSymbolAddress((void**)&feat1,   g_feat1);
    cudaGetSymbolAddress((void**)&bias_qkv, g_bias_qkv);
    cudaGetSymbolAddress((void**)&f16,     g_feat16);
    cudaGetSymbolAddress((void**)&hn16,    g_hn16);
    cudaGetSymbolAddress((void**)&vt16,    g_vt16);
    cudaGetSymbolAddress((void**)&hmid16,  g_hmid16);
    cudaGetSymbolAddress((void**)&h_wh,    g_wh);

    cudaFuncSetAttribute(gemm_fp16_kernel,
                         cudaFuncAttributeMaxDynamicSharedMemorySize, SM_TOTAL);
    cudaFuncSetAttribute(gemm_stream_kernel,
                         cudaFuncAttributeMaxDynamicSharedMemorySize, SMS_TOTAL);
    cudaFuncSetAttribute(gemm_stream_f32_kernel,
                         cudaFuncAttributeMaxDynamicSharedMemorySize, SMS_TOTAL);

    float* out_feat  = (float*)d_out;
    float* out_efeat = (float*)d_out + (size_t)N * CC;
    __half* q16 = qkv16;
    __half* k16 = qkv16 + (size_t)N * CC;
    __half* v16 = qkv16 + (size_t)2 * N * CC;

    // 0) one-time prep
    conv_weights_kernel<<<(WBF_TOTAL + 255) / 256, 256>>>(
        Wq, Wk, Wv, W_rel, Wproj, WeW, W1, W2, bq, bk, bv, h_wh, bias_qkv);
    prep_kernel<<<1024, 256>>>(feat, f16, (size_t)N * CC,
                               den, (size_t)N * HH, wv, (size_t)N * CC);

    // 1) fused q+k+v (stream kernel, grid.y = 3, fp16 out; 294 CTAs = 1 wave @2/SM)
    gemm_stream_kernel<<<dim3(98, 3), 256, SMS_TOTAL>>>(
        f16, CC, h_wh + WOFF_Q, CC, 16384, 0,
        bias_qkv, CC,
        nullptr, CC, (size_t)N * CC,
        qkv16, 2, N, 0, nBlkN);

    // 2) vt16[t] = v16 @ W_rel[t] (stream kernel, grid.y = 8; 296 CTAs)
    gemm_stream_kernel<<<dim3(37, TT), 256, SMS_TOTAL>>>(
        v16, CC, h_wh + WOFF_REL, CC, 16384, 0,
        nullptr, 0,
        nullptr, CC, (size_t)N * CC,
        vt16, 2, N, 0, nBlkN);

    // 3) edge scores + denominators
    {
        long total = (long)E * HH;
        score_kernel<<<(int)((total + 255) / 256), 256>>>(q16, k16, src, dst, esc, den, E);
    }
    // 4) edge aggregation
    {
        long total = (long)E * 16;
        agg_kernel<<<(int)((total + 255) / 256), 256>>>(vt16, efeat, esc, den,
                                                        src, dst, etype, wv, E, N);
    }

    // 5) feat1 = feat + wv @ Wproj + bproj  (fp32-A stream, B resident)
    gemm_stream_f32_kernel<<<296, 256, SMS_TOTAL>>>(
        wv, CC, h_wh + WOFF_PROJ, CC, bproj, feat, feat1, CC, N, nBlkN);

    // 6) hn = layernorm(feat1) -> fp16
    {
        long total = (long)N * 32;
        ln_kernel<<<(int)((total + 255) / 256), 256>>>(feat1, ln_g, ln_b, hn16, N);
    }

    // 7) hmid16 = gelu(hn @ W1 + b1)  (stream kernel, grid.y = 4; 296 CTAs)
    gemm_stream_kernel<<<dim3(74, 4), 256, SMS_TOTAL>>>(
        hn16, CC, h_wh + WOFF_W1, 4 * CC, 0, 128,
        b1, 0,
        nullptr, 4 * CC, 0,
        hmid16, 2, N, 1, nBlkN);

    // 8) feat_out = feat1 + hmid16 @ W2 + b2  (fp16 A, K = 512, R12 kernel)
    gemm_fp16_kernel<<<dim3(nBlkN, 1), 256, SM_TOTAL>>>(
        hmid16, 4 * CC, 4 * CC, h_wh + WOFF_W2, CC,
        b2, feat1, out_feat, CC, N);

    // 9) efeat_out = efeat @ WeW + beW  (fp32-A stream, B resident, persistent)
    gemm_stream_f32_kernel<<<296, 256, SMS_TOTAL>>>(
        efeat, CC, h_wh + WOFF_EW, CC, beW, nullptr, out_efeat, CC, E, nBlkE);
}